// round 10
// baseline (speedup 1.0000x reference)
#include <cuda_runtime.h>

#define BB 16
#define NN 4096
#define SS 512
#define KK 32
#define MM (BB*SS*KK)   // 262144 rows
#define NBLK 1024       // layer-kernel grid (MM/256)

typedef unsigned long long u64;

__device__ __forceinline__ u64 pack2(float lo, float hi) {
    u64 r; asm("mov.b64 %0, {%1,%2};" : "=l"(r) : "f"(lo), "f"(hi)); return r;
}
__device__ __forceinline__ void unpack2(u64 v, float& lo, float& hi) {
    asm("mov.b64 {%0,%1}, %2;" : "=f"(lo), "=f"(hi) : "l"(v));
}
__device__ __forceinline__ u64 ffma2(u64 a, u64 b, u64 c) {
    u64 r; asm("fma.rn.f32x2 %0, %1, %2, %3;" : "=l"(r) : "l"(a), "l"(b), "l"(c)); return r;
}

// ---------------- scratch (device globals; no allocations) ----------------
__device__ float g_newxyz[BB*SS*3];
__device__ float g_ptnorm[BB*NN];
__device__ float g_qnorm[BB*SS];
__device__ int   g_fps[BB*SS];
__device__ int   g_gidx[MM];
__device__ float g_feat0[64u*MM];     // 67 MB, layout [ch][row]
__device__ float g_feat1[64u*MM];     // 67 MB
__device__ float g_maxv[BB*SS*128];   // 4 MB  pre-BN max over K
__device__ float g_minv[BB*SS*128];   // 4 MB  pre-BN min over K
__device__ float g_psum[128*NBLK];    // fp32 per (channel, block) partial sums
__device__ float g_psq [128*NBLK];
__device__ float g_scale[3][128];
__device__ float g_shift[3][128];

// ---------------- 1) FPS: points register-resident; SMEM only for centroid ----
__global__ void fps_kernel(const float* __restrict__ xyz)
{
    __shared__ float redv[2][16];
    __shared__ int   redi[2][16];
    extern __shared__ float sh[];
    float* sx = sh;
    float* sy = sh + NN;
    float* sz = sh + 2*NN;

    int b   = blockIdx.x;
    int tid = threadIdx.x;
    const float* xb = xyz + (size_t)b*NN*3;

    float px[8], py[8], pz[8], dist[8];
#pragma unroll
    for (int j = 0; j < 8; j++) {
        int i = j*512 + tid;
        float x = xb[i*3+0], y = xb[i*3+1], z = xb[i*3+2];
        px[j] = x; py[j] = y; pz[j] = z;
        sx[i] = x; sy[i] = y; sz[i] = z;
        dist[j] = 1e10f;
    }
    __syncthreads();

    int lane = tid & 31, w = tid >> 5;
    int cur = 0;
    float cx = sx[0], cy = sy[0], cz = sz[0];

    for (int it = 0; it < SS; ++it) {
        float bv = -1.0f; int bi = 0;
#pragma unroll
        for (int j = 0; j < 8; j++) {
            float dx = px[j] - cx, dy = py[j] - cy, dz = pz[j] - cz;
            float d  = dx*dx + dy*dy + dz*dz;
            d = fminf(dist[j], d);
            dist[j] = d;
            if (d > bv) { bv = d; bi = j*512 + tid; }   // ascending j: > keeps first
        }
        // warp argmax, ties -> smaller index
#pragma unroll
        for (int off = 16; off; off >>= 1) {
            float ov = __shfl_down_sync(0xffffffffu, bv, off);
            int   oi = __shfl_down_sync(0xffffffffu, bi, off);
            if (ov > bv || (ov == bv && oi < bi)) { bv = ov; bi = oi; }
        }
        int buf = it & 1;
        if (lane == 0) { redv[buf][w] = bv; redi[buf][w] = bi; }
        __syncthreads();
        float mv = redv[buf][0]; int mi = redi[buf][0];
#pragma unroll
        for (int q = 1; q < 16; q++) {
            float v = redv[buf][q]; int i2 = redi[buf][q];
            if (v > mv || (v == mv && i2 < mi)) { mv = v; mi = i2; }
        }
        if (tid == 0) g_fps[b*SS + it] = cur;   // record OLD farthest (scan semantics)
        cur = mi;
        cx = sx[mi]; cy = sy[mi]; cz = sz[mi];
    }
}

// ---------------- 2) gather new_xyz + precompute norms ----------------
__global__ void gather_kernel(const float* __restrict__ xyz, float* __restrict__ out)
{
    int t = blockIdx.x*256 + threadIdx.x;     // covers BB*NN = 65536
    if (t < BB*NN) {
        float x = xyz[t*3], y = xyz[t*3+1], z = xyz[t*3+2];
        g_ptnorm[t] = x*x + y*y + z*z;
    }
    if (t < BB*SS) {
        int b = t / SS;
        int idx = g_fps[t];
        const float* p = xyz + ((size_t)(b*NN + idx))*3;
        float x = p[0], y = p[1], z = p[2];
        g_newxyz[t*3+0] = x; g_newxyz[t*3+1] = y; g_newxyz[t*3+2] = z;
        out[t*3+0] = x; out[t*3+1] = y; out[t*3+2] = z;
        g_qnorm[t] = x*x + y*y + z*z;
    }
}

// ---------------- 3) ball query: one warp per query point ----------------
__global__ void query_kernel(const float* __restrict__ xyz)
{
    extern __shared__ float sh[];
    float* sx = sh;
    float* sy = sh + NN;
    float* sz = sh + 2*NN;
    float* sn = sh + 3*NN;

    int b = blockIdx.y;
    int tid = threadIdx.x;
    const float* xb = xyz + (size_t)b*NN*3;
    for (int i = tid; i < NN; i += 256) {
        sx[i] = xb[i*3+0]; sy[i] = xb[i*3+1]; sz[i] = xb[i*3+2];
        sn[i] = g_ptnorm[b*NN + i];
    }
    __syncthreads();

    int w = tid >> 5, lane = tid & 31;
    int s = blockIdx.x*8 + w;
    int bs = b*SS + s;
    float qx = g_newxyz[bs*3+0], qy = g_newxyz[bs*3+1], qz = g_newxyz[bs*3+2];
    float qn = g_qnorm[bs];
    int base = bs*KK;

    int cnt = 0, first = 0;
    const float R2 = 0.04f;   // f32(radius**2) as JAX weak-types it
    for (int ch = 0; ch < NN/32 && cnt < KK; ++ch) {
        int i = ch*32 + lane;
        float dot = sx[i]*qx + sy[i]*qy + sz[i]*qz;
        float d = (-2.0f*dot + qn) + sn[i];       // match reference add order
        bool ok = !(d > R2);
        unsigned m = __ballot_sync(0xffffffffu, ok);
        if (m) {
            if (cnt == 0) first = ch*32 + __ffs(m) - 1;
            int pos = cnt + __popc(m & ((1u << lane) - 1u));
            if (ok && pos < KK) g_gidx[base + pos] = i;
            cnt += __popc(m);
        }
    }
    for (int p = cnt + lane; p < KK; p += 32) g_gidx[base + p] = first;
}

// ================= shared epilogue (stats via SMEM transpose, fp32) ==========

// ---------------- 4) gather features + layer0 (6 -> 64) + fused stats ---------
__global__ __launch_bounds__(256) void layer0_kernel(
    const float* __restrict__ xyz, const float* __restrict__ pts,
    const float* __restrict__ w0, const float* __restrict__ b0)
{
    extern __shared__ char smraw[];
    float* sfsum = (float*)smraw;                // 512
    float* sfsq  = sfsum + 512;                  // 512
    float* wT    = sfsq + 512;                   // 384
    float* sb    = wT + 6*64;                    // 64
    float* sacc  = sb + 64;                      // 8*64*33

    int tid = threadIdx.x;
    for (int i = tid; i < 6*64; i += 256) {
        int c = i >> 6, o = i & 63;
        wT[c*64 + o] = w0[o*6 + c];
    }
    if (tid < 64) sb[tid] = b0[tid];
    __syncthreads();

    int row = blockIdx.x*256 + tid;
    int b = row >> 14;             // SS*KK = 16384
    int r = row & 16383;
    int s = r >> 5;
    int idx = g_gidx[row];
    const float* g  = xyz + ((size_t)(b*NN + idx))*3;
    const float* nx = g_newxyz + (size_t)(b*SS + s)*3;
    const float* pp = pts + ((size_t)(b*NN + idx))*3;

    float f[6];
    f[0] = g[0] - nx[0]; f[1] = g[1] - nx[1]; f[2] = g[2] - nx[2];
    f[3] = pp[0]; f[4] = pp[1]; f[5] = pp[2];

    float acc[64];
#pragma unroll
    for (int o = 0; o < 64; o++) acc[o] = sb[o];
#pragma unroll
    for (int c = 0; c < 6; c++) {
        float v = f[c];
        const float4* wr = (const float4*)(wT + c*64);
#pragma unroll
        for (int q = 0; q < 16; q++) {
            float4 wv = wr[q];
            acc[4*q+0] = fmaf(v, wv.x, acc[4*q+0]);
            acc[4*q+1] = fmaf(v, wv.y, acc[4*q+1]);
            acc[4*q+2] = fmaf(v, wv.z, acc[4*q+2]);
            acc[4*q+3] = fmaf(v, wv.w, acc[4*q+3]);
        }
    }
#pragma unroll
    for (int o = 0; o < 64; o++) g_feat0[(size_t)o*MM + row] = acc[o];

    // fused stats (fp32)
    int w = tid >> 5, lane = tid & 31;
#pragma unroll
    for (int o = 0; o < 64; o++) sacc[(w*64 + o)*33 + lane] = acc[o];
    __syncthreads();
    for (int p = tid; p < 512; p += 256) {
        int w2 = p >> 6, o = p & 63;
        const float* src = sacc + (w2*64 + o)*33;
        float sv = 0.0f, sq = 0.0f;
#pragma unroll
        for (int l = 0; l < 32; l++) {
            float v = src[l];
            sv += v; sq = fmaf(v, v, sq);
        }
        sfsum[o*8 + w2] = sv; sfsq[o*8 + w2] = sq;
    }
    __syncthreads();
    if (tid < 64) {
        float S = 0.0f, Q = 0.0f;
#pragma unroll
        for (int w2 = 0; w2 < 8; w2++) { S += sfsum[tid*8 + w2]; Q += sfsq[tid*8 + w2]; }
        g_psum[tid*NBLK + blockIdx.x] = S;
        g_psq [tid*NBLK + blockIdx.x] = Q;
    }
}

// ---------------- 5) finalize BN stats: one block per channel (double here) ----
__global__ void fin_kernel(int li, const float* __restrict__ gamma, const float* __restrict__ beta)
{
    int c = blockIdx.x;
    double s = 0.0, q = 0.0;
    for (int j = threadIdx.x; j < NBLK; j += 256) {
        s += (double)g_psum[c*NBLK + j];
        q += (double)g_psq [c*NBLK + j];
    }
    __shared__ double rs[8], rq[8];
#pragma unroll
    for (int off = 16; off; off >>= 1) {
        s += __shfl_down_sync(0xffffffffu, s, off);
        q += __shfl_down_sync(0xffffffffu, q, off);
    }
    int lane = threadIdx.x & 31, w = threadIdx.x >> 5;
    if (lane == 0) { rs[w] = s; rq[w] = q; }
    __syncthreads();
    if (threadIdx.x == 0) {
        double S = 0.0, Q = 0.0;
        for (int k = 0; k < 8; k++) { S += rs[k]; Q += rq[k]; }
        double md = S / (double)MM;
        float mean = (float)md;
        float var  = (float)(Q / (double)MM - md*md);
        float istd = rsqrtf(var + 1e-5f);
        float sc = istd * gamma[c];
        g_scale[li][c] = sc;
        g_shift[li][c] = beta[c] - mean*sc;
    }
}

// ---------------- 6) layer1: BN0+ReLU in, 64->64 via f32x2, feat1 + stats ------
__global__ __launch_bounds__(256) void mid_kernel(const float* __restrict__ w, const float* __restrict__ bias)
{
    extern __shared__ char smraw[];
    float* sfsum = (float*)smraw;                // 512
    float* sfsq  = sfsum + 512;                  // 512
    float* wT    = sfsq + 512;                   // 4096
    float* sb    = wT + 64*64;                   // 64
    float* ssc   = sb + 64;                      // 64
    float* ssh   = ssc + 64;                     // 64
    float* sacc  = ssh + 64;                     // 8*64*33

    int tid = threadIdx.x;
    for (int i = tid; i < 64*64; i += 256) {
        int c = i >> 6, o = i & 63;
        wT[c*64 + o] = w[(size_t)o*64 + c];
    }
    if (tid < 64) {
        sb[tid]  = bias[tid];
        ssc[tid] = g_scale[0][tid];
        ssh[tid] = g_shift[0][tid];
    }
    __syncthreads();

    int row = blockIdx.x*256 + tid;
    u64 acc2[32];
#pragma unroll
    for (int q = 0; q < 32; q++) acc2[q] = pack2(sb[2*q], sb[2*q+1]);
#pragma unroll 4
    for (int c = 0; c < 64; c++) {
        float x = g_feat0[(size_t)c*MM + row];
        float v = fmaxf(fmaf(x, ssc[c], ssh[c]), 0.0f);
        u64 vv = pack2(v, v);
        const ulonglong2* wr = (const ulonglong2*)(wT + c*64);
#pragma unroll
        for (int q = 0; q < 16; q++) {
            ulonglong2 wv = wr[q];
            acc2[2*q+0] = ffma2(vv, wv.x, acc2[2*q+0]);
            acc2[2*q+1] = ffma2(vv, wv.y, acc2[2*q+1]);
        }
    }
    float acc[64];
#pragma unroll
    for (int q = 0; q < 32; q++) unpack2(acc2[q], acc[2*q], acc[2*q+1]);
#pragma unroll
    for (int o = 0; o < 64; o++) g_feat1[(size_t)o*MM + row] = acc[o];

    // fused stats (fp32)
    int wd = tid >> 5, lane = tid & 31;
#pragma unroll
    for (int o = 0; o < 64; o++) sacc[(wd*64 + o)*33 + lane] = acc[o];
    __syncthreads();
    for (int p = tid; p < 512; p += 256) {
        int w2 = p >> 6, o = p & 63;
        const float* src = sacc + (w2*64 + o)*33;
        float sv = 0.0f, sq = 0.0f;
#pragma unroll
        for (int l = 0; l < 32; l++) {
            float v = src[l];
            sv += v; sq = fmaf(v, v, sq);
        }
        sfsum[o*8 + w2] = sv; sfsq[o*8 + w2] = sq;
    }
    __syncthreads();
    if (tid < 64) {
        float S = 0.0f, Q = 0.0f;
#pragma unroll
        for (int w2 = 0; w2 < 8; w2++) { S += sfsum[tid*8 + w2]; Q += sfsq[tid*8 + w2]; }
        g_psum[tid*NBLK + blockIdx.x] = S;
        g_psq [tid*NBLK + blockIdx.x] = Q;
    }
}

// ---------------- 7) layer2: BN1+ReLU in, 64->64 slice via f32x2, K-pool + stats
// grid (NBLK, 2): blockIdx.y selects output slice (o_base = y*64). No feat2 store.
__global__ __launch_bounds__(256) void layer2_kernel(const float* __restrict__ w, const float* __restrict__ bias)
{
    extern __shared__ char smraw[];
    float* sfsum = (float*)smraw;
    float* sfsq  = sfsum + 512;
    float* wT    = sfsq + 512;
    float* sb    = wT + 64*64;
    float* ssc   = sb + 64;
    float* ssh   = ssc + 64;
    float* sacc  = ssh + 64;

    int o_base = blockIdx.y*64;
    int tid = threadIdx.x;
    for (int i = tid; i < 64*64; i += 256) {
        int c = i >> 6, o = i & 63;
        wT[c*64 + o] = w[(size_t)(o_base + o)*64 + c];
    }
    if (tid < 64) {
        sb[tid]  = bias[o_base + tid];
        ssc[tid] = g_scale[1][tid];
        ssh[tid] = g_shift[1][tid];
    }
    __syncthreads();

    int row = blockIdx.x*256 + tid;
    u64 acc2[32];
#pragma unroll
    for (int q = 0; q < 32; q++) acc2[q] = pack2(sb[2*q], sb[2*q+1]);
#pragma unroll 4
    for (int c = 0; c < 64; c++) {
        float x = g_feat1[(size_t)c*MM + row];
        float v = fmaxf(fmaf(x, ssc[c], ssh[c]), 0.0f);
        u64 vv = pack2(v, v);
        const ulonglong2* wr = (const ulonglong2*)(wT + c*64);
#pragma unroll
        for (int q = 0; q < 16; q++) {
            ulonglong2 wv = wr[q];
            acc2[2*q+0] = ffma2(vv, wv.x, acc2[2*q+0]);
            acc2[2*q+1] = ffma2(vv, wv.y, acc2[2*q+1]);
        }
    }
    float acc[64];
#pragma unroll
    for (int q = 0; q < 32; q++) unpack2(acc2[q], acc[2*q], acc[2*q+1]);

    // fused maxpool(min) over K (one warp == one (b,s) group) + stats (fp32)
    int wd = tid >> 5, lane = tid & 31;
#pragma unroll
    for (int o = 0; o < 64; o++) sacc[(wd*64 + o)*33 + lane] = acc[o];
    __syncthreads();
    for (int p = tid; p < 512; p += 256) {
        int w2 = p >> 6, o = p & 63;
        const float* src = sacc + (w2*64 + o)*33;
        float mx = -3.402823466e38f, mn = 3.402823466e38f;
        float sv = 0.0f, sq = 0.0f;
#pragma unroll
        for (int l = 0; l < 32; l++) {
            float v = src[l];
            mx = fmaxf(mx, v); mn = fminf(mn, v);
            sv += v; sq = fmaf(v, v, sq);
        }
        sfsum[o*8 + w2] = sv; sfsq[o*8 + w2] = sq;
        int bs = blockIdx.x*8 + w2;
        g_maxv[bs*128 + o_base + o] = mx;
        g_minv[bs*128 + o_base + o] = mn;
    }
    __syncthreads();
    if (tid < 64) {
        float S = 0.0f, Q = 0.0f;
#pragma unroll
        for (int w2 = 0; w2 < 8; w2++) { S += sfsum[tid*8 + w2]; Q += sfsq[tid*8 + w2]; }
        g_psum[(o_base + tid)*NBLK + blockIdx.x] = S;
        g_psq [(o_base + tid)*NBLK + blockIdx.x] = Q;
    }
}

// ---------------- 8) final: BN2+ReLU applied to K-extremes ----------------
__global__ void final_kernel(float* __restrict__ out)
{
    int i = blockIdx.x*256 + threadIdx.x;      // BB*SS*128 = 1048576
    int o = i & 127;
    float sc = g_scale[2][o], shv = g_shift[2][o];
    float e = (sc >= 0.0f) ? g_maxv[i] : g_minv[i];
    out[BB*SS*3 + i] = fmaxf(fmaf(sc, e, shv), 0.0f);
}

// ---------------- launch ----------------
extern "C" void kernel_launch(void* const* d_in, const int* in_sizes, int n_in,
                              void* d_out, int out_size)
{
    const float* xyz    = (const float*)d_in[0];
    const float* pts    = (const float*)d_in[1];
    const float* w0     = (const float*)d_in[2];
    const float* b0     = (const float*)d_in[3];
    const float* gamma0 = (const float*)d_in[4];
    const float* beta0  = (const float*)d_in[5];
    const float* w1     = (const float*)d_in[6];
    const float* b1     = (const float*)d_in[7];
    const float* gamma1 = (const float*)d_in[8];
    const float* beta1  = (const float*)d_in[9];
    const float* w2     = (const float*)d_in[10];
    const float* b2     = (const float*)d_in[11];
    const float* gamma2 = (const float*)d_in[12];
    const float* beta2  = (const float*)d_in[13];
    float* out = (float*)d_out;

    const int SM_L0  = (512*2 + 6*64 + 64 + 8*64*33)*4;
    const int SM_MID = (512*2 + 64*64 + 3*64 + 8*64*33)*4;

    cudaFuncSetAttribute(fps_kernel,    cudaFuncAttributeMaxDynamicSharedMemorySize, 3*NN*4);
    cudaFuncSetAttribute(query_kernel,  cudaFuncAttributeMaxDynamicSharedMemorySize, 4*NN*4);
    cudaFuncSetAttribute(layer0_kernel, cudaFuncAttributeMaxDynamicSharedMemorySize, SM_L0);
    cudaFuncSetAttribute(mid_kernel,    cudaFuncAttributeMaxDynamicSharedMemorySize, SM_MID);
    cudaFuncSetAttribute(layer2_kernel, cudaFuncAttributeMaxDynamicSharedMemorySize, SM_MID);

    fps_kernel<<<BB, 512, 3*NN*4>>>(xyz);
    gather_kernel<<<(BB*NN)/256, 256>>>(xyz, out);
    query_kernel<<<dim3(SS/8, BB), 256, 4*NN*4>>>(xyz);

    layer0_kernel<<<NBLK, 256, SM_L0>>>(xyz, pts, w0, b0);
    fin_kernel<<<64, 256>>>(0, gamma0, beta0);

    mid_kernel<<<NBLK, 256, SM_MID>>>(w1, b1);
    fin_kernel<<<64, 256>>>(1, gamma1, beta1);

    layer2_kernel<<<dim3(NBLK, 2), 256, SM_MID>>>(w2, b2);
    fin_kernel<<<128, 256>>>(2, gamma2, beta2);

    final_kernel<<<(BB*SS*128)/256, 256>>>(out);
}

// round 13
// speedup vs baseline: 1.5048x; 1.5048x over previous
#include <cuda_runtime.h>

#define BB 16
#define NN 4096
#define SS 512
#define KK 32
#define MM (BB*SS*KK)   // 262144 rows
#define NBLK 1024       // layer-kernel grid (MM/256)

// ---------------- scratch (device globals; no allocations) ----------------
__device__ float g_newxyz[BB*SS*3];
__device__ float g_ptnorm[BB*NN];
__device__ float g_qnorm[BB*SS];
__device__ int   g_fps[BB*SS];
__device__ int   g_gidx[MM];
__device__ float g_feat0[64u*MM];     // 67 MB, layout [ch][row]
__device__ float g_feat1[64u*MM];     // 67 MB
__device__ float g_maxv[BB*SS*128];   // 4 MB  pre-BN max over K
__device__ float g_minv[BB*SS*128];   // 4 MB  pre-BN min over K
__device__ float g_psum[128*NBLK];    // fp32 per (channel, block) partial sums
__device__ float g_psq [128*NBLK];
__device__ float g_scale[3][128];
__device__ float g_shift[3][128];

// ---------------- 1) FPS: points register-resident; SMEM only for centroid ----
__global__ void fps_kernel(const float* __restrict__ xyz)
{
    __shared__ float redv[2][16];
    __shared__ int   redi[2][16];
    extern __shared__ float sh[];
    float* sx = sh;
    float* sy = sh + NN;
    float* sz = sh + 2*NN;

    int b   = blockIdx.x;
    int tid = threadIdx.x;
    const float* xb = xyz + (size_t)b*NN*3;

    float px[8], py[8], pz[8], dist[8];
#pragma unroll
    for (int j = 0; j < 8; j++) {
        int i = j*512 + tid;
        float x = xb[i*3+0], y = xb[i*3+1], z = xb[i*3+2];
        px[j] = x; py[j] = y; pz[j] = z;
        sx[i] = x; sy[i] = y; sz[i] = z;
        dist[j] = 1e10f;
    }
    __syncthreads();

    int lane = tid & 31, w = tid >> 5;
    int cur = 0;
    float cx = sx[0], cy = sy[0], cz = sz[0];

    for (int it = 0; it < SS; ++it) {
        float bv = -1.0f; int bi = 0;
#pragma unroll
        for (int j = 0; j < 8; j++) {
            float dx = px[j] - cx, dy = py[j] - cy, dz = pz[j] - cz;
            float d  = dx*dx + dy*dy + dz*dz;
            d = fminf(dist[j], d);
            dist[j] = d;
            if (d > bv) { bv = d; bi = j*512 + tid; }   // ascending j: > keeps first
        }
        // warp argmax, ties -> smaller index
#pragma unroll
        for (int off = 16; off; off >>= 1) {
            float ov = __shfl_down_sync(0xffffffffu, bv, off);
            int   oi = __shfl_down_sync(0xffffffffu, bi, off);
            if (ov > bv || (ov == bv && oi < bi)) { bv = ov; bi = oi; }
        }
        int buf = it & 1;
        if (lane == 0) { redv[buf][w] = bv; redi[buf][w] = bi; }
        __syncthreads();
        float mv = redv[buf][0]; int mi = redi[buf][0];
#pragma unroll
        for (int q = 1; q < 16; q++) {
            float v = redv[buf][q]; int i2 = redi[buf][q];
            if (v > mv || (v == mv && i2 < mi)) { mv = v; mi = i2; }
        }
        if (tid == 0) g_fps[b*SS + it] = cur;   // record OLD farthest (scan semantics)
        cur = mi;
        cx = sx[mi]; cy = sy[mi]; cz = sz[mi];
    }
}

// ---------------- 2) gather new_xyz + precompute norms ----------------
__global__ void gather_kernel(const float* __restrict__ xyz, float* __restrict__ out)
{
    int t = blockIdx.x*256 + threadIdx.x;     // covers BB*NN = 65536
    if (t < BB*NN) {
        float x = xyz[t*3], y = xyz[t*3+1], z = xyz[t*3+2];
        g_ptnorm[t] = x*x + y*y + z*z;
    }
    if (t < BB*SS) {
        int b = t / SS;
        int idx = g_fps[t];
        const float* p = xyz + ((size_t)(b*NN + idx))*3;
        float x = p[0], y = p[1], z = p[2];
        g_newxyz[t*3+0] = x; g_newxyz[t*3+1] = y; g_newxyz[t*3+2] = z;
        out[t*3+0] = x; out[t*3+1] = y; out[t*3+2] = z;
        g_qnorm[t] = x*x + y*y + z*z;
    }
}

// ---------------- 3) ball query: one warp per query point ----------------
__global__ void query_kernel(const float* __restrict__ xyz)
{
    extern __shared__ float sh[];
    float* sx = sh;
    float* sy = sh + NN;
    float* sz = sh + 2*NN;
    float* sn = sh + 3*NN;

    int b = blockIdx.y;
    int tid = threadIdx.x;
    const float* xb = xyz + (size_t)b*NN*3;
    for (int i = tid; i < NN; i += 256) {
        sx[i] = xb[i*3+0]; sy[i] = xb[i*3+1]; sz[i] = xb[i*3+2];
        sn[i] = g_ptnorm[b*NN + i];
    }
    __syncthreads();

    int w = tid >> 5, lane = tid & 31;
    int s = blockIdx.x*8 + w;
    int bs = b*SS + s;
    float qx = g_newxyz[bs*3+0], qy = g_newxyz[bs*3+1], qz = g_newxyz[bs*3+2];
    float qn = g_qnorm[bs];
    int base = bs*KK;

    int cnt = 0, first = 0;
    const float R2 = 0.04f;   // f32(radius**2) as JAX weak-types it
    for (int ch = 0; ch < NN/32 && cnt < KK; ++ch) {
        int i = ch*32 + lane;
        float dot = sx[i]*qx + sy[i]*qy + sz[i]*qz;
        float d = (-2.0f*dot + qn) + sn[i];       // match reference add order
        bool ok = !(d > R2);
        unsigned m = __ballot_sync(0xffffffffu, ok);
        if (m) {
            if (cnt == 0) first = ch*32 + __ffs(m) - 1;
            int pos = cnt + __popc(m & ((1u << lane) - 1u));
            if (ok && pos < KK) g_gidx[base + pos] = i;
            cnt += __popc(m);
        }
    }
    for (int p = cnt + lane; p < KK; p += 32) g_gidx[base + p] = first;
}

// ================= shared epilogue (stats via SMEM transpose, fp32) ==========

// ---------------- 4) gather features + layer0 (6 -> 64) + fused stats ---------
__global__ __launch_bounds__(256) void layer0_kernel(
    const float* __restrict__ xyz, const float* __restrict__ pts,
    const float* __restrict__ w0, const float* __restrict__ b0)
{
    extern __shared__ char smraw[];
    float* sfsum = (float*)smraw;                // 512
    float* sfsq  = sfsum + 512;                  // 512
    float* wT    = sfsq + 512;                   // 384
    float* sb    = wT + 6*64;                    // 64
    float* sacc  = sb + 64;                      // 8*64*33

    int tid = threadIdx.x;
    for (int i = tid; i < 6*64; i += 256) {
        int c = i >> 6, o = i & 63;
        wT[c*64 + o] = w0[o*6 + c];
    }
    if (tid < 64) sb[tid] = b0[tid];
    __syncthreads();

    int row = blockIdx.x*256 + tid;
    int b = row >> 14;             // SS*KK = 16384
    int r = row & 16383;
    int s = r >> 5;
    int idx = g_gidx[row];
    const float* g  = xyz + ((size_t)(b*NN + idx))*3;
    const float* nx = g_newxyz + (size_t)(b*SS + s)*3;
    const float* pp = pts + ((size_t)(b*NN + idx))*3;

    float f[6];
    f[0] = g[0] - nx[0]; f[1] = g[1] - nx[1]; f[2] = g[2] - nx[2];
    f[3] = pp[0]; f[4] = pp[1]; f[5] = pp[2];

    float acc[64];
#pragma unroll
    for (int o = 0; o < 64; o++) acc[o] = sb[o];
#pragma unroll
    for (int c = 0; c < 6; c++) {
        float v = f[c];
        const float4* wr = (const float4*)(wT + c*64);
#pragma unroll
        for (int q = 0; q < 16; q++) {
            float4 wv = wr[q];
            acc[4*q+0] = fmaf(v, wv.x, acc[4*q+0]);
            acc[4*q+1] = fmaf(v, wv.y, acc[4*q+1]);
            acc[4*q+2] = fmaf(v, wv.z, acc[4*q+2]);
            acc[4*q+3] = fmaf(v, wv.w, acc[4*q+3]);
        }
    }
#pragma unroll
    for (int o = 0; o < 64; o++) g_feat0[(size_t)o*MM + row] = acc[o];

    // fused stats (fp32)
    int w = tid >> 5, lane = tid & 31;
#pragma unroll
    for (int o = 0; o < 64; o++) sacc[(w*64 + o)*33 + lane] = acc[o];
    __syncthreads();
    for (int p = tid; p < 512; p += 256) {
        int w2 = p >> 6, o = p & 63;
        const float* src = sacc + (w2*64 + o)*33;
        float sv = 0.0f, sq = 0.0f;
#pragma unroll
        for (int l = 0; l < 32; l++) {
            float v = src[l];
            sv += v; sq = fmaf(v, v, sq);
        }
        sfsum[o*8 + w2] = sv; sfsq[o*8 + w2] = sq;
    }
    __syncthreads();
    if (tid < 64) {
        float S = 0.0f, Q = 0.0f;
#pragma unroll
        for (int w2 = 0; w2 < 8; w2++) { S += sfsum[tid*8 + w2]; Q += sfsq[tid*8 + w2]; }
        g_psum[tid*NBLK + blockIdx.x] = S;
        g_psq [tid*NBLK + blockIdx.x] = Q;
    }
}

// ---------------- 5) finalize BN stats: one block per channel (double here) ----
__global__ void fin_kernel(int li, const float* __restrict__ gamma, const float* __restrict__ beta)
{
    int c = blockIdx.x;
    double s = 0.0, q = 0.0;
    for (int j = threadIdx.x; j < NBLK; j += 256) {
        s += (double)g_psum[c*NBLK + j];
        q += (double)g_psq [c*NBLK + j];
    }
    __shared__ double rs[8], rq[8];
#pragma unroll
    for (int off = 16; off; off >>= 1) {
        s += __shfl_down_sync(0xffffffffu, s, off);
        q += __shfl_down_sync(0xffffffffu, q, off);
    }
    int lane = threadIdx.x & 31, w = threadIdx.x >> 5;
    if (lane == 0) { rs[w] = s; rq[w] = q; }
    __syncthreads();
    if (threadIdx.x == 0) {
        double S = 0.0, Q = 0.0;
        for (int k = 0; k < 8; k++) { S += rs[k]; Q += rq[k]; }
        double md = S / (double)MM;
        float mean = (float)md;
        float var  = (float)(Q / (double)MM - md*md);
        float istd = rsqrtf(var + 1e-5f);
        float sc = istd * gamma[c];
        g_scale[li][c] = sc;
        g_shift[li][c] = beta[c] - mean*sc;
    }
}

// ---------------- 6) layer1: BN0+ReLU on input, 64->64, store feat1 + stats ----
__global__ __launch_bounds__(256) void mid_kernel(const float* __restrict__ w, const float* __restrict__ bias)
{
    extern __shared__ char smraw[];
    float* sfsum = (float*)smraw;                // 512
    float* sfsq  = sfsum + 512;                  // 512
    float* wT    = sfsq + 512;                   // 4096
    float* sb    = wT + 64*64;                   // 64
    float* ssc   = sb + 64;                      // 64
    float* ssh   = ssc + 64;                     // 64
    float* sacc  = ssh + 64;                     // 8*64*33

    int tid = threadIdx.x;
    for (int i = tid; i < 64*64; i += 256) {
        int c = i >> 6, o = i & 63;
        wT[c*64 + o] = w[(size_t)o*64 + c];
    }
    if (tid < 64) {
        sb[tid]  = bias[tid];
        ssc[tid] = g_scale[0][tid];
        ssh[tid] = g_shift[0][tid];
    }
    __syncthreads();

    int row = blockIdx.x*256 + tid;
    float acc[64];
#pragma unroll
    for (int o = 0; o < 64; o++) acc[o] = sb[o];
#pragma unroll 8
    for (int c = 0; c < 64; c++) {
        float x = g_feat0[(size_t)c*MM + row];
        float v = fmaxf(fmaf(x, ssc[c], ssh[c]), 0.0f);
        const float4* wr = (const float4*)(wT + c*64);
#pragma unroll
        for (int q = 0; q < 16; q++) {
            float4 wv = wr[q];
            acc[4*q+0] = fmaf(v, wv.x, acc[4*q+0]);
            acc[4*q+1] = fmaf(v, wv.y, acc[4*q+1]);
            acc[4*q+2] = fmaf(v, wv.z, acc[4*q+2]);
            acc[4*q+3] = fmaf(v, wv.w, acc[4*q+3]);
        }
    }
#pragma unroll
    for (int o = 0; o < 64; o++) g_feat1[(size_t)o*MM + row] = acc[o];

    // fused stats (fp32)
    int wd = tid >> 5, lane = tid & 31;
#pragma unroll
    for (int o = 0; o < 64; o++) sacc[(wd*64 + o)*33 + lane] = acc[o];
    __syncthreads();
    for (int p = tid; p < 512; p += 256) {
        int w2 = p >> 6, o = p & 63;
        const float* src = sacc + (w2*64 + o)*33;
        float sv = 0.0f, sq = 0.0f;
#pragma unroll
        for (int l = 0; l < 32; l++) {
            float v = src[l];
            sv += v; sq = fmaf(v, v, sq);
        }
        sfsum[o*8 + w2] = sv; sfsq[o*8 + w2] = sq;
    }
    __syncthreads();
    if (tid < 64) {
        float S = 0.0f, Q = 0.0f;
#pragma unroll
        for (int w2 = 0; w2 < 8; w2++) { S += sfsum[tid*8 + w2]; Q += sfsq[tid*8 + w2]; }
        g_psum[tid*NBLK + blockIdx.x] = S;
        g_psq [tid*NBLK + blockIdx.x] = Q;
    }
}

// ---------------- 7) layer2: BN1+ReLU in, 64->64 slice, fused K-max/min + stats ----
// grid (NBLK, 2): blockIdx.y selects output slice (o_base = y*64). No feat2 store.
__global__ __launch_bounds__(256) void layer2_kernel(const float* __restrict__ w, const float* __restrict__ bias)
{
    extern __shared__ char smraw[];
    float* sfsum = (float*)smraw;
    float* sfsq  = sfsum + 512;
    float* wT    = sfsq + 512;
    float* sb    = wT + 64*64;
    float* ssc   = sb + 64;
    float* ssh   = ssc + 64;
    float* sacc  = ssh + 64;

    int o_base = blockIdx.y*64;
    int tid = threadIdx.x;
    for (int i = tid; i < 64*64; i += 256) {
        int c = i >> 6, o = i & 63;
        wT[c*64 + o] = w[(size_t)(o_base + o)*64 + c];
    }
    if (tid < 64) {
        sb[tid]  = bias[o_base + tid];
        ssc[tid] = g_scale[1][tid];
        ssh[tid] = g_shift[1][tid];
    }
    __syncthreads();

    int row = blockIdx.x*256 + tid;
    float acc[64];
#pragma unroll
    for (int o = 0; o < 64; o++) acc[o] = sb[o];
#pragma unroll 8
    for (int c = 0; c < 64; c++) {
        float x = g_feat1[(size_t)c*MM + row];
        float v = fmaxf(fmaf(x, ssc[c], ssh[c]), 0.0f);
        const float4* wr = (const float4*)(wT + c*64);
#pragma unroll
        for (int q = 0; q < 16; q++) {
            float4 wv = wr[q];
            acc[4*q+0] = fmaf(v, wv.x, acc[4*q+0]);
            acc[4*q+1] = fmaf(v, wv.y, acc[4*q+1]);
            acc[4*q+2] = fmaf(v, wv.z, acc[4*q+2]);
            acc[4*q+3] = fmaf(v, wv.w, acc[4*q+3]);
        }
    }

    // fused maxpool(min) over K (one warp == one (b,s) group) + stats (fp32)
    int wd = tid >> 5, lane = tid & 31;
#pragma unroll
    for (int o = 0; o < 64; o++) sacc[(wd*64 + o)*33 + lane] = acc[o];
    __syncthreads();
    for (int p = tid; p < 512; p += 256) {
        int w2 = p >> 6, o = p & 63;
        const float* src = sacc + (w2*64 + o)*33;
        float mx = -3.402823466e38f, mn = 3.402823466e38f;
        float sv = 0.0f, sq = 0.0f;
#pragma unroll
        for (int l = 0; l < 32; l++) {
            float v = src[l];
            mx = fmaxf(mx, v); mn = fminf(mn, v);
            sv += v; sq = fmaf(v, v, sq);
        }
        sfsum[o*8 + w2] = sv; sfsq[o*8 + w2] = sq;
        int bs = blockIdx.x*8 + w2;
        g_maxv[bs*128 + o_base + o] = mx;
        g_minv[bs*128 + o_base + o] = mn;
    }
    __syncthreads();
    if (tid < 64) {
        float S = 0.0f, Q = 0.0f;
#pragma unroll
        for (int w2 = 0; w2 < 8; w2++) { S += sfsum[tid*8 + w2]; Q += sfsq[tid*8 + w2]; }
        g_psum[(o_base + tid)*NBLK + blockIdx.x] = S;
        g_psq [(o_base + tid)*NBLK + blockIdx.x] = Q;
    }
}

// ---------------- 8) final: BN2+ReLU applied to K-extremes ----------------
__global__ void final_kernel(float* __restrict__ out)
{
    int i = blockIdx.x*256 + threadIdx.x;      // BB*SS*128 = 1048576
    int o = i & 127;
    float sc = g_scale[2][o], shv = g_shift[2][o];
    float e = (sc >= 0.0f) ? g_maxv[i] : g_minv[i];
    out[BB*SS*3 + i] = fmaxf(fmaf(sc, e, shv), 0.0f);
}

// ---------------- launch ----------------
extern "C" void kernel_launch(void* const* d_in, const int* in_sizes, int n_in,
                              void* d_out, int out_size)
{
    const float* xyz    = (const float*)d_in[0];
    const float* pts    = (const float*)d_in[1];
    const float* w0     = (const float*)d_in[2];
    const float* b0     = (const float*)d_in[3];
    const float* gamma0 = (const float*)d_in[4];
    const float* beta0  = (const float*)d_in[5];
    const float* w1     = (const float*)d_in[6];
    const float* b1     = (const float*)d_in[7];
    const float* gamma1 = (const float*)d_in[8];
    const float* beta1  = (const float*)d_in[9];
    const float* w2     = (const float*)d_in[10];
    const float* b2     = (const float*)d_in[11];
    const float* gamma2 = (const float*)d_in[12];
    const float* beta2  = (const float*)d_in[13];
    float* out = (float*)d_out;

    const int SM_L0  = (512*2 + 6*64 + 64 + 8*64*33)*4;
    const int SM_MID = (512*2 + 64*64 + 3*64 + 8*64*33)*4;

    cudaFuncSetAttribute(fps_kernel,    cudaFuncAttributeMaxDynamicSharedMemorySize, 3*NN*4);
    cudaFuncSetAttribute(query_kernel,  cudaFuncAttributeMaxDynamicSharedMemorySize, 4*NN*4);
    cudaFuncSetAttribute(layer0_kernel, cudaFuncAttributeMaxDynamicSharedMemorySize, SM_L0);
    cudaFuncSetAttribute(mid_kernel,    cudaFuncAttributeMaxDynamicSharedMemorySize, SM_MID);
    cudaFuncSetAttribute(layer2_kernel, cudaFuncAttributeMaxDynamicSharedMemorySize, SM_MID);

    fps_kernel<<<BB, 512, 3*NN*4>>>(xyz);
    gather_kernel<<<(BB*NN)/256, 256>>>(xyz, out);
    query_kernel<<<dim3(SS/8, BB), 256, 4*NN*4>>>(xyz);

    layer0_kernel<<<NBLK, 256, SM_L0>>>(xyz, pts, w0, b0);
    fin_kernel<<<64, 256>>>(0, gamma0, beta0);

    mid_kernel<<<NBLK, 256, SM_MID>>>(w1, b1);
    fin_kernel<<<64, 256>>>(1, gamma1, beta1);

    layer2_kernel<<<dim3(NBLK, 2), 256, SM_MID>>>(w2, b2);
    fin_kernel<<<128, 256>>>(2, gamma2, beta2);

    final_kernel<<<(BB*SS*128)/256, 256>>>(out);
}